// round 7
// baseline (speedup 1.0000x reference)
#include <cuda_runtime.h>

// Output is identically zero: g = -sum((x - x)^2) == 0 elementwise, so
// w = C*g == 0 and lambda_tri = mask @ w == 0. Kernel = 64 KB zero-fill.
//
// Grid-shape U-curve measured (device dur, 1 STG.128/thread unless noted):
//   1x1024 (4/thr): 4.35us   (single-SM LSU serialization)
//   16x256:         3.68us
//   32x128:         3.33us   <- minimum (wall 4.608us)
//   64x64:          3.65us
//   128x32:         4.54us   (per-block dispatch overhead)
// Node type (kernel vs native memset) and per-thread work are also converged.
// Lock in 32 blocks x 128 threads, one float4 store per thread.

__global__ __launch_bounds__(128, 1)
void zero_fill(float4* __restrict__ out) {
    // 32 blocks x 128 threads = 4096 float4 = 16384 floats = 64 KB.
    out[(blockIdx.x << 7) | threadIdx.x] = make_float4(0.f, 0.f, 0.f, 0.f);
}

__global__ void zero_generic(float* __restrict__ out, int n) {
    int i = blockIdx.x * blockDim.x + threadIdx.x;
    if (i < n) out[i] = 0.f;
}

extern "C" void kernel_launch(void* const* d_in, const int* in_sizes, int n_in,
                              void* d_out, int out_size) {
    (void)d_in; (void)in_sizes; (void)n_in;
    if (out_size == 16384) {
        zero_fill<<<32, 128>>>((float4*)d_out);
    } else {
        int threads = 256;
        int blocks = (out_size + threads - 1) / threads;
        zero_generic<<<blocks, threads>>>((float*)d_out, out_size);
    }
}

// round 8
// speedup vs baseline: 1.1184x; 1.1184x over previous
#include <cuda_runtime.h>

// Output is identically zero: g = -sum((x - x)^2) == 0 elementwise, so
// w = C*g == 0 and lambda_tri = mask @ w == 0. Kernel = 64 KB zero-fill.
//
// CONVERGED. Evidence:
//  - Node type: kernel node == native memset node (both 4.864us wall, R1/R2).
//  - Per-thread work: 1 STG.128/thread optimal (4/thread on 1 SM regressed, R3).
//  - Grid shape: extremes are real regressions (1 blk: dev 4.35; 128 blk: dev
//    4.54); 16/32/64-block shapes are statistically indistinguishable.
//  - Noise: identical 32x128 binary measured dev 3.33/wall 4.61 (R4) and
//    dev 3.62/wall 5.44 (R7) -> +/-0.3us dev, +/-0.8us wall run-to-run.
// Remaining time is launch ramp + graph replay overhead; 8ns of store traffic
// cannot be made cheaper than the launch carrying it.

__global__ __launch_bounds__(128, 1)
void zero_fill(float4* __restrict__ out) {
    // 32 blocks x 128 threads = 4096 float4 = 16384 floats = 64 KB.
    out[(blockIdx.x << 7) | threadIdx.x] = make_float4(0.f, 0.f, 0.f, 0.f);
}

__global__ void zero_generic(float* __restrict__ out, int n) {
    int i = blockIdx.x * blockDim.x + threadIdx.x;
    if (i < n) out[i] = 0.f;
}

extern "C" void kernel_launch(void* const* d_in, const int* in_sizes, int n_in,
                              void* d_out, int out_size) {
    (void)d_in; (void)in_sizes; (void)n_in;
    if (out_size == 16384) {
        zero_fill<<<32, 128>>>((float4*)d_out);
    } else {
        int threads = 256;
        int blocks = (out_size + threads - 1) / threads;
        zero_generic<<<blocks, threads>>>((float*)d_out, out_size);
    }
}

// round 9
// speedup vs baseline: 1.1888x; 1.0629x over previous
#include <cuda_runtime.h>

// Output is identically zero: g = -sum((x - x)^2) == 0 elementwise, so
// w = C*g == 0 and lambda_tri = mask @ w == 0. Kernel = 64 KB zero-fill.
//
// CONVERGED — holding this kernel. Evidence across 8 rounds:
//  - Node type: kernel node == native memset node (R1/R2, both 4.864us wall).
//  - Per-thread work: 1 STG.128/thread optimal (4/thread single-SM regressed, R3).
//  - Grid shape: 1 blk (dev 4.35) and 128 blk (dev 4.54) are real regressions;
//    16/32/64-block shapes statistically indistinguishable (3.3-3.7us dev).
//  - Noise: identical 32x128 binary sampled wall {4.608, 5.440, 4.864}us
//    (R4/R7/R8) -> sigma ~0.35us; occ/issue % wiggle with identical SASS.
// Remaining time = launch ramp (~3.5us) + graph replay (~1.3us). 8ns of store
// traffic cannot be made cheaper than the launch that carries it.

__global__ __launch_bounds__(128, 1)
void zero_fill(float4* __restrict__ out) {
    // 32 blocks x 128 threads = 4096 float4 = 16384 floats = 64 KB.
    out[(blockIdx.x << 7) | threadIdx.x] = make_float4(0.f, 0.f, 0.f, 0.f);
}

__global__ void zero_generic(float* __restrict__ out, int n) {
    int i = blockIdx.x * blockDim.x + threadIdx.x;
    if (i < n) out[i] = 0.f;
}

extern "C" void kernel_launch(void* const* d_in, const int* in_sizes, int n_in,
                              void* d_out, int out_size) {
    (void)d_in; (void)in_sizes; (void)n_in;
    if (out_size == 16384) {
        zero_fill<<<32, 128>>>((float4*)d_out);
    } else {
        int threads = 256;
        int blocks = (out_size + threads - 1) / threads;
        zero_generic<<<blocks, threads>>>((float*)d_out, out_size);
    }
}